// round 4
// baseline (speedup 1.0000x reference)
#include <cuda_runtime.h>

#define BB 8192
#define TT 512
#define KK 12
#define GPB 8                        // batches per forward block
#define FWD_THREADS (GPB * KK)       // 96 = 3 warps
#define BT_THREADS 32

// Packed backpointers: row (t,b) = u64, nibble j = best prev tag for tag j at t.
__device__ unsigned long long g_bp[(size_t)TT * BB];   // 33.5 MB
// Final trellis row (t = T-1) values, [B][12] floats.
__device__ float g_final[(size_t)BB * KK];
__device__ float g_scores_scratch[BB];

// ---------------------------------------------------------------------------
// First-index-wins select (matches jnp.argmax tie-breaking): >= keeps left,
// and every merge's left operand covers strictly smaller indices.
// ---------------------------------------------------------------------------
__device__ __forceinline__ void sel2(float a, int ia, float b, int ib,
                                     float& ov, int& oi) {
    bool p = (a >= b);
    ov = p ? a : b;
    oi = p ? ia : ib;
}

// argmax over 11 candidates (indices 0..10); row 11 is provably never the
// argmax (transitions[11][:] = -1000 while prev[11] stays within O(1) of max).
__device__ __forceinline__ void amax11(const float* v, float& bv, int& bi) {
    float s0, s1, s2, s3, s4;
    int   i0, i1, i2, i3, i4;
    sel2(v[0], 0, v[1], 1, s0, i0);
    sel2(v[2], 2, v[3], 3, s1, i1);
    sel2(v[4], 4, v[5], 5, s2, i2);
    sel2(v[6], 6, v[7], 7, s3, i3);
    sel2(v[8], 8, v[9], 9, s4, i4);
    float t0, t1, t2; int k0, k1, k2;
    sel2(s0, i0, s1, i1, t0, k0);
    sel2(s2, i2, s3, i3, t1, k1);
    sel2(s4, i4, v[10], 10, t2, k2);
    float u; int ku;
    sel2(t0, k0, t1, k1, u, ku);
    sel2(u, ku, t2, k2, bv, bi);
}

__device__ __forceinline__ void amax12(const float* v, float& bv, int& bi) {
    float s0, s1, s2, s3, s4, s5;
    int   i0, i1, i2, i3, i4, i5;
    sel2(v[0],  0,  v[1],  1,  s0, i0);
    sel2(v[2],  2,  v[3],  3,  s1, i1);
    sel2(v[4],  4,  v[5],  5,  s2, i2);
    sel2(v[6],  6,  v[7],  7,  s3, i3);
    sel2(v[8],  8,  v[9],  9,  s4, i4);
    sel2(v[10], 10, v[11], 11, s5, i5);
    float t0, t1, t2; int k0, k1, k2;
    sel2(s0, i0, s1, i1, t0, k0);
    sel2(s2, i2, s3, i3, t1, k1);
    sel2(s4, i4, s5, i5, t2, k2);
    float u; int ku;
    sel2(t0, k0, t1, k1, u, ku);
    sel2(u, ku, t2, k2, bv, bi);
}

// ---------------------------------------------------------------------------
// Forward: 1 tag per thread, 12 threads per batch, 8 batches per block.
// Double-buffered smem exchange, one barrier per step, 2-deep emission prefetch.
// ---------------------------------------------------------------------------
__global__ __launch_bounds__(FWD_THREADS) void viterbi_fwd(
    const float* __restrict__ logits,   // [B, T, K]
    const float* __restrict__ trans)    // [K, K], trans[i*K+j] = i -> j
{
    __shared__ __align__(16) float buf[2][GPB][16];  // 64B group stride

    const int tid = threadIdx.x;
    const int g = tid / KK;
    const int j = tid - g * KK;
    const size_t b = (size_t)blockIdx.x * GPB + g;

    // Transition column j, rows 0..10 only (row 11 never wins).
    float tc[11];
#pragma unroll
    for (int i = 0; i < 11; i++) tc[i] = __ldg(trans + i * KK + j);

    const float* em = logits + b * TT * KK + j;
    unsigned char* bp8 = (unsigned char*)g_bp;
    const bool evenj = ((j & 1) == 0);
    const int halfj = j >> 1;

    // t = 0: prev row = emissions
    float best = __ldcs(em);
    buf[0][g][j] = best;

    // 2-deep emission prefetch (t = 1, 2)
    float en1 = __ldcs(em + KK);
    float en2 = __ldcs(em + 2 * KK);

#pragma unroll 2
    for (int t = 1; t < TT; t++) {
        __syncthreads();
        const float* r = &buf[(t - 1) & 1][g][0];
        float4 p0 = *(const float4*)(r);
        float4 p1 = *(const float4*)(r + 4);
        float4 p2 = *(const float4*)(r + 8);

        const float e = en1;
        en1 = en2;
        const int tn = (t + 2 < TT) ? (t + 2) : (TT - 1);
        en2 = __ldcs(em + (size_t)tn * KK);

        float v[11];
        v[0]  = p0.x + tc[0];  v[1]  = p0.y + tc[1];
        v[2]  = p0.z + tc[2];  v[3]  = p0.w + tc[3];
        v[4]  = p1.x + tc[4];  v[5]  = p1.y + tc[5];
        v[6]  = p1.z + tc[6];  v[7]  = p1.w + tc[7];
        v[8]  = p2.x + tc[8];  v[9]  = p2.y + tc[9];
        v[10] = p2.z + tc[10];

        float m; int a;
        amax11(v, m, a);

        best = m + e;
        buf[t & 1][g][j] = best;

        // Pack two 4-bit backpointers per byte; pairs are always intra-warp.
        int other = __shfl_down_sync(0xffffffffu, a, 1);
        if (evenj)
            bp8[((size_t)t * BB + b) * 8 + halfj] =
                (unsigned char)(a | (other << 4));
    }

    g_final[b * KK + j] = best;
}

// ---------------------------------------------------------------------------
// Backtrace: one thread per batch, 16-deep software-pipelined bp row loads,
// path written via 4-wide register buffer (STG.128).
// ---------------------------------------------------------------------------
__global__ __launch_bounds__(BT_THREADS) void viterbi_btr(
    float* __restrict__ scores,   // [B]
    float* __restrict__ paths)    // [B, T] as float
{
    const size_t b = (size_t)blockIdx.x * BT_THREADS + threadIdx.x;

    float v[12];
    {
        const float4* row = (const float4*)(g_final + b * KK);
        float4 r0 = __ldg(&row[0]), r1 = __ldg(&row[1]), r2 = __ldg(&row[2]);
        v[0] = r0.x; v[1] = r0.y; v[2]  = r0.z; v[3]  = r0.w;
        v[4] = r1.x; v[5] = r1.y; v[6]  = r1.z; v[7]  = r1.w;
        v[8] = r2.x; v[9] = r2.y; v[10] = r2.z; v[11] = r2.w;
    }
    float bv; int cur;
    amax12(v, bv, cur);
    scores[b] = bv;

    float* po = paths + b * TT;
    float pbuf[4];
    pbuf[3] = (float)cur;   // path[T-1]

    const unsigned long long* bp = g_bp;

    unsigned long long r[16], rn[16];
    int t = TT - 1;   // 511
#pragma unroll
    for (int i = 0; i < 16; i++)
        r[i] = __ldg(bp + (size_t)(t - i) * BB + b);

    for (int grp = 0; grp < 31; grp++) {
#pragma unroll
        for (int i = 0; i < 16; i++) {
            int tl = t - 16 - i;
            rn[i] = __ldg(bp + (size_t)tl * BB + b);
        }
#pragma unroll
        for (int i = 0; i < 16; i++) {
            const int tt = t - i;
            const int nx = (int)((r[i] >> (cur * 4)) & 15ull);
            pbuf[(tt - 1) & 3] = (float)nx;
            if (((tt - 1) & 3) == 0)
                *(float4*)(po + (tt - 1)) = make_float4(pbuf[0], pbuf[1], pbuf[2], pbuf[3]);
            cur = nx;
        }
#pragma unroll
        for (int i = 0; i < 16; i++) r[i] = rn[i];
        t -= 16;
    }
#pragma unroll
    for (int i = 0; i < 15; i++) {
        const int tt = 15 - i;
        const int nx = (int)((r[i] >> (cur * 4)) & 15ull);
        pbuf[(tt - 1) & 3] = (float)nx;
        if (((tt - 1) & 3) == 0)
            *(float4*)(po + (tt - 1)) = make_float4(pbuf[0], pbuf[1], pbuf[2], pbuf[3]);
        cur = nx;
    }
}

// ---------------------------------------------------------------------------
// Launch
// ---------------------------------------------------------------------------
extern "C" void kernel_launch(void* const* d_in, const int* in_sizes, int n_in,
                              void* d_out, int out_size) {
    const float* logits = (const float*)d_in[0];
    const float* trans  = (const float*)d_in[1];
    if (n_in >= 2 && in_sizes[0] == KK * KK) {  // robustness: swapped inputs
        const float* tmp = logits; logits = trans; trans = tmp;
    }

    viterbi_fwd<<<BB / GPB, FWD_THREADS>>>(logits, trans);

    float* out = (float*)d_out;
    float* scores;
    float* paths;
    float* d_scores_scratch = nullptr;
    cudaGetSymbolAddress((void**)&d_scores_scratch, g_scores_scratch);

    if (out_size >= BB * TT + BB) {
        scores = out;            // [scores (B) | paths (B*T)]
        paths = out + BB;
    } else if (out_size == BB * TT) {
        scores = d_scores_scratch;
        paths = out;
    } else {
        scores = out;
        float* d_bp = nullptr;
        cudaGetSymbolAddress((void**)&d_bp, g_bp);
        paths = (float*)d_bp;    // dead scratch as sink
    }

    viterbi_btr<<<BB / BT_THREADS, BT_THREADS>>>(scores, paths);
}

// round 5
// speedup vs baseline: 1.1205x; 1.1205x over previous
#include <cuda_runtime.h>

#define BB 8192
#define TT 512
#define KK 12

#define GPW 6                        // batch groups per warp (5 lanes each)
#define WPB 5                        // warps per block
#define GPB (GPW * WPB)              // 30 batches per block
#define FWD_THREADS (WPB * 32)       // 160
#define NBLK ((BB + GPB - 1) / GPB)  // 274 (tail groups duplicate batch BB-1)
#define AMASK 0x3fffffffu            // lanes 0..29 active
#define BT_THREADS 32

// Packed backpointers: row (t,b) = u64; nibble j = best prev tag for tag j at t.
__device__ unsigned long long g_bp[(size_t)TT * BB];   // 33.5 MB
// Final trellis row values, [B][12] floats (slot 10 = -1e30 sentinel).
__device__ float g_final[(size_t)BB * KK];
__device__ float g_scores_scratch[BB];

// ---------------------------------------------------------------------------
// f32x2 packed helpers (sm_100+). add.rn.f32x2 is bit-exact vs scalar FADD RN.
// ---------------------------------------------------------------------------
__device__ __forceinline__ unsigned long long pack2(float lo, float hi) {
    unsigned long long r;
    asm("mov.b64 %0, {%1, %2};" : "=l"(r) : "f"(lo), "f"(hi));
    return r;
}
__device__ __forceinline__ void unpack2(unsigned long long v, float& lo, float& hi) {
    asm("mov.b64 {%0, %1}, %2;" : "=f"(lo), "=f"(hi) : "l"(v));
}
__device__ __forceinline__ unsigned long long add2(unsigned long long a,
                                                   unsigned long long b) {
    unsigned long long r;
    asm("add.rn.f32x2 %0, %1, %2;" : "=l"(r) : "l"(a), "l"(b));
    return r;
}

// ---------------------------------------------------------------------------
// First-index-wins select (matches jnp.argmax): >= keeps left; every merge's
// left operand covers strictly smaller indices.
// ---------------------------------------------------------------------------
__device__ __forceinline__ void sel2(float a, int ia, float b, int ib,
                                     float& ov, int& oi) {
    bool p = (a >= b);
    ov = p ? a : b;
    oi = p ? ia : ib;
}

// argmax over candidates 0..9 (i=10,11 provably never win for t>=2).
__device__ __forceinline__ void amax10(const float* v, float& bv, int& bi) {
    float s0, s1, s2, s3, s4;
    int   i0, i1, i2, i3, i4;
    sel2(v[0], 0, v[1], 1, s0, i0);
    sel2(v[2], 2, v[3], 3, s1, i1);
    sel2(v[4], 4, v[5], 5, s2, i2);
    sel2(v[6], 6, v[7], 7, s3, i3);
    sel2(v[8], 8, v[9], 9, s4, i4);
    float t0, t1; int k0, k1;
    sel2(s0, i0, s1, i1, t0, k0);
    sel2(s2, i2, s3, i3, t1, k1);
    float u; int ku;
    sel2(t0, k0, t1, k1, u, ku);
    sel2(u, ku, s4, i4, bv, bi);
}

__device__ __forceinline__ void amax12(const float* v, float& bv, int& bi) {
    float s0, s1, s2, s3, s4, s5;
    int   i0, i1, i2, i3, i4, i5;
    sel2(v[0],  0,  v[1],  1,  s0, i0);
    sel2(v[2],  2,  v[3],  3,  s1, i1);
    sel2(v[4],  4,  v[5],  5,  s2, i2);
    sel2(v[6],  6,  v[7],  7,  s3, i3);
    sel2(v[8],  8,  v[9],  9,  s4, i4);
    sel2(v[10], 10, v[11], 11, s5, i5);
    float t0, t1, t2; int k0, k1, k2;
    sel2(s0, i0, s1, i1, t0, k0);
    sel2(s2, i2, s3, i3, t1, k1);
    sel2(s4, i4, s5, i5, t2, k2);
    float u; int ku;
    sel2(t0, k0, t1, k1, u, ku);
    sel2(u, ku, t2, k2, bv, bi);
}

// ---------------------------------------------------------------------------
// Forward: 5 lanes per batch (2 tags each), 6 batches per warp, warp-local
// smem exchange with __syncwarp only (no block barriers). Packed f32x2 adds.
// Tag chains j=0..9 only; j=11 computed once at t=511 by lane 0; j=10 never.
// ---------------------------------------------------------------------------
__global__ __launch_bounds__(FWD_THREADS) void viterbi_fwd(
    const float* __restrict__ logits,   // [B, T, K]
    const float* __restrict__ trans)    // [K, K], trans[i*K+j] = i -> j
{
    __shared__ __align__(16) float buf[2][GPB][12];   // 48B rows

    const int lane = threadIdx.x & 31;
    const int wid = threadIdx.x >> 5;
    if (lane >= 30) return;
    const int gl = lane / 5;                 // group within warp
    const int k = lane - gl * 5;             // lane within group: tags 2k, 2k+1
    const int g = wid * GPW + gl;            // group within block
    size_t b = (size_t)blockIdx.x * GPB + g;
    if (b >= BB) b = BB - 1;                 // tail duplicates (same-value writes)
    const int j0 = 2 * k;

    // Packed transition pairs: tcc0[i] = (trans[2i][j0],   trans[2i+1][j0])
    //                          tcc1[i] = (trans[2i][j0+1], trans[2i+1][j0+1])
    unsigned long long tcc0[5], tcc1[5];
#pragma unroll
    for (int i = 0; i < 5; i++) {
        tcc0[i] = pack2(__ldg(trans + (2 * i) * KK + j0),
                        __ldg(trans + (2 * i + 1) * KK + j0));
        tcc1[i] = pack2(__ldg(trans + (2 * i) * KK + j0 + 1),
                        __ldg(trans + (2 * i + 1) * KK + j0 + 1));
    }
    // t=1 extra candidate i=10
    const float tca = __ldg(trans + 10 * KK + j0);
    const float tcb = __ldg(trans + 10 * KK + j0 + 1);
    // lane 0: transition column 11 (rows 0..9) for the final j=11 chain
    float tcl[10];
    if (k == 0) {
#pragma unroll
        for (int i = 0; i < 10; i++) tcl[i] = __ldg(trans + i * KK + 11);
    }

    const float* em = logits + b * TT * KK;
    unsigned char* bp8 = (unsigned char*)g_bp;

    // t=0: prev row = emissions (tags 0..9, plus em[0][10] for the t=1 peel)
    {
        float2 e0 = __ldg((const float2*)(em + j0));
        *(float2*)&buf[0][g][j0] = e0;
        if (k == 0) buf[0][g][10] = __ldg(em + 10);
    }
    float2 en1 = __ldg((const float2*)(em + KK + j0));        // row 1
    float2 en2 = __ldg((const float2*)(em + 2 * KK + j0));    // row 2
    __syncwarp(AMASK);

    float best0, best1;

    // ---- peeled t = 1: candidates i = 0..10 ----
    {
        const unsigned long long* rp = (const unsigned long long*)&buf[0][g][0];
        unsigned long long r0 = rp[0], r1 = rp[1], r2 = rp[2], r3 = rp[3], r4 = rp[4];
        const float em10 = buf[0][g][10];

        float v[10], w[10];
        unpack2(add2(r0, tcc0[0]), v[0], v[1]);
        unpack2(add2(r1, tcc0[1]), v[2], v[3]);
        unpack2(add2(r2, tcc0[2]), v[4], v[5]);
        unpack2(add2(r3, tcc0[3]), v[6], v[7]);
        unpack2(add2(r4, tcc0[4]), v[8], v[9]);
        unpack2(add2(r0, tcc1[0]), w[0], w[1]);
        unpack2(add2(r1, tcc1[1]), w[2], w[3]);
        unpack2(add2(r2, tcc1[2]), w[4], w[5]);
        unpack2(add2(r3, tcc1[3]), w[6], w[7]);
        unpack2(add2(r4, tcc1[4]), w[8], w[9]);

        float m0, m1; int a0, a1;
        amax10(v, m0, a0);
        amax10(w, m1, a1);
        sel2(m0, a0, em10 + tca, 10, m0, a0);   // candidate i=10 viable at t=1
        sel2(m1, a1, em10 + tcb, 10, m1, a1);

        best0 = m0 + en1.x;
        best1 = m1 + en1.y;
        *(float2*)&buf[1][g][j0] = make_float2(best0, best1);
        bp8[((size_t)1 * BB + b) * 8 + k] = (unsigned char)(a0 | (a1 << 4));
    }
    en1 = en2;
    en2 = __ldg((const float2*)(em + 3 * KK + j0));

    // ---- main loop t = 2..511: candidates i = 0..9 ----
#pragma unroll 2
    for (int t = 2; t < TT; t++) {
        __syncwarp(AMASK);
        const unsigned long long* rp =
            (const unsigned long long*)&buf[(t - 1) & 1][g][0];
        unsigned long long r0 = rp[0], r1 = rp[1], r2 = rp[2], r3 = rp[3], r4 = rp[4];

        const float ex = en1.x, ey = en1.y;
        en1 = en2;
        const int tn = (t + 2 < TT) ? (t + 2) : (TT - 1);
        en2 = __ldg((const float2*)(em + (size_t)tn * KK + j0));

        float v[10], w[10];
        unpack2(add2(r0, tcc0[0]), v[0], v[1]);
        unpack2(add2(r1, tcc0[1]), v[2], v[3]);
        unpack2(add2(r2, tcc0[2]), v[4], v[5]);
        unpack2(add2(r3, tcc0[3]), v[6], v[7]);
        unpack2(add2(r4, tcc0[4]), v[8], v[9]);
        unpack2(add2(r0, tcc1[0]), w[0], w[1]);
        unpack2(add2(r1, tcc1[1]), w[2], w[3]);
        unpack2(add2(r2, tcc1[2]), w[4], w[5]);
        unpack2(add2(r3, tcc1[3]), w[6], w[7]);
        unpack2(add2(r4, tcc1[4]), w[8], w[9]);

        float m0, m1; int a0, a1;
        amax10(v, m0, a0);
        amax10(w, m1, a1);

        best0 = m0 + ex;
        best1 = m1 + ey;
        *(float2*)&buf[t & 1][g][j0] = make_float2(best0, best1);
        bp8[((size_t)t * BB + b) * 8 + k] = (unsigned char)(a0 | (a1 << 4));
    }

    // final row values for tags 0..9
    *(float2*)(g_final + b * KK + j0) = make_float2(best0, best1);

    // lane 0: tag 11 at t=511 from row 510 (buf[0], synced at top of t=511)
    if (k == 0) {
        const unsigned long long* rp = (const unsigned long long*)&buf[0][g][0];
        float p[10];
        unpack2(rp[0], p[0], p[1]);
        unpack2(rp[1], p[2], p[3]);
        unpack2(rp[2], p[4], p[5]);
        unpack2(rp[3], p[6], p[7]);
        unpack2(rp[4], p[8], p[9]);
        float c[10];
#pragma unroll
        for (int i = 0; i < 10; i++) c[i] = p[i] + tcl[i];
        float m11; int a11;
        amax10(c, m11, a11);
        float b11 = m11 + __ldg(em + (size_t)(TT - 1) * KK + 11);
        *(float2*)(g_final + b * KK + 10) = make_float2(-1e30f, b11);
        bp8[((size_t)(TT - 1) * BB + b) * 8 + 5] = (unsigned char)(a11 << 4);
    }
}

// ---------------------------------------------------------------------------
// Backtrace: one thread per batch; 3-group-deep (48 loads) software pipeline
// so the dependent nibble chain never waits on DRAM. STG.128 path writes.
// ---------------------------------------------------------------------------
#define PROC(Rarr, TBASE, CNT)                                                 \
    do {                                                                       \
        _Pragma("unroll") for (int i = 0; i < (CNT); i++) {                    \
            const int tt = (TBASE) - i;                                        \
            const int nx = (int)((Rarr[i] >> (cur * 4)) & 15ull);              \
            pbuf[(tt - 1) & 3] = (float)nx;                                    \
            if (((tt - 1) & 3) == 0)                                           \
                *(float4*)(po + (tt - 1)) =                                    \
                    make_float4(pbuf[0], pbuf[1], pbuf[2], pbuf[3]);           \
            cur = nx;                                                          \
        }                                                                      \
    } while (0)

#define LOADG(Rarr, GIDX)                                                      \
    do {                                                                       \
        if ((GIDX) < 32) {                                                     \
            const int ts = 511 - 16 * (GIDX);                                  \
            _Pragma("unroll") for (int i = 0; i < 16; i++)                     \
                Rarr[i] = __ldg(bp + (size_t)(ts - i) * BB + b);               \
        }                                                                      \
    } while (0)

__global__ __launch_bounds__(BT_THREADS) void viterbi_btr(
    float* __restrict__ scores,   // [B]
    float* __restrict__ paths)    // [B, T] as float
{
    const size_t b = (size_t)blockIdx.x * BT_THREADS + threadIdx.x;

    float v[12];
    {
        const float4* row = (const float4*)(g_final + b * KK);
        float4 r0 = __ldg(&row[0]), r1 = __ldg(&row[1]), r2 = __ldg(&row[2]);
        v[0] = r0.x; v[1] = r0.y; v[2]  = r0.z; v[3]  = r0.w;
        v[4] = r1.x; v[5] = r1.y; v[6]  = r1.z; v[7]  = r1.w;
        v[8] = r2.x; v[9] = r2.y; v[10] = r2.z; v[11] = r2.w;
    }
    float bv; int cur;
    amax12(v, bv, cur);
    scores[b] = bv;

    float* po = paths + b * TT;
    float pbuf[4];
    pbuf[3] = (float)cur;   // path[T-1]

    const unsigned long long* bp = g_bp;

    unsigned long long R0[16], R1[16], R2[16];
    LOADG(R0, 0);
    LOADG(R1, 1);
    LOADG(R2, 2);

    // 32 groups: 31 full (16 rows) + tail (15 rows). Process 3, reload 3.
#pragma unroll 1
    for (int m = 0; m < 10; m++) {
        const int g0 = 3 * m;
        PROC(R0, 511 - 16 * g0, 16);        LOADG(R0, g0 + 3);
        PROC(R1, 511 - 16 * (g0 + 1), 16);  LOADG(R1, g0 + 4);
        PROC(R2, 511 - 16 * (g0 + 2), 16);  LOADG(R2, g0 + 5);
    }
    PROC(R0, 511 - 16 * 30, 16);   // group 30: t = 31..16
    PROC(R1, 511 - 16 * 31, 15);   // group 31 (tail): t = 15..1
}

// ---------------------------------------------------------------------------
// Launch
// ---------------------------------------------------------------------------
extern "C" void kernel_launch(void* const* d_in, const int* in_sizes, int n_in,
                              void* d_out, int out_size) {
    const float* logits = (const float*)d_in[0];
    const float* trans  = (const float*)d_in[1];
    if (n_in >= 2 && in_sizes[0] == KK * KK) {  // robustness: swapped inputs
        const float* tmp = logits; logits = trans; trans = tmp;
    }

    viterbi_fwd<<<NBLK, FWD_THREADS>>>(logits, trans);

    float* out = (float*)d_out;
    float* scores;
    float* paths;
    float* d_scores_scratch = nullptr;
    cudaGetSymbolAddress((void**)&d_scores_scratch, g_scores_scratch);

    if (out_size >= BB * TT + BB) {
        scores = out;            // [scores (B) | paths (B*T)]
        paths = out + BB;
    } else if (out_size == BB * TT) {
        scores = d_scores_scratch;
        paths = out;
    } else {
        scores = out;
        float* d_bp = nullptr;
        cudaGetSymbolAddress((void**)&d_bp, g_bp);
        paths = (float*)d_bp;    // dead scratch as sink
    }

    viterbi_btr<<<BB / BT_THREADS, BT_THREADS>>>(scores, paths);
}